// round 1
// baseline (speedup 1.0000x reference)
#include <cuda_runtime.h>
#include <cstdint>

#define B_  2
#define S_  2048
#define H_  2048
#define NH  16
#define HD  128
#define M_  (B_*S_)

// Scratch (static device allocations are allowed; cudaMalloc is not)
__device__ float g_q[(size_t)B_*NH*S_*HD];    // [b,h,s,d]
__device__ float g_k[(size_t)B_*NH*S_*HD];
__device__ float g_v[(size_t)B_*NH*S_*HD];
__device__ float g_ctx[(size_t)B_*S_*H_];     // [b,s,h]

// ---------------------------------------------------------------------------
// SGEMM (NT): C[M,N] = A[M,K] * W[N,K]^T + bias[N]
// BM=BN=128, BK=8, 256 threads, 8x8 micro-tile per thread.
// MODE 0: scatter into qkv [b,h,s,d] layout.  MODE 1: plain [M,N] store.
// ---------------------------------------------------------------------------
template<int MODE>
__global__ __launch_bounds__(256) void sgemm_nt(
    const float* __restrict__ A, const float* __restrict__ W,
    const float* __restrict__ bias, float* __restrict__ out)
{
    const int K = H_;
    __shared__ float As[8][128];
    __shared__ float Bs[8][128];
    const int tid = threadIdx.x;
    const int bm = blockIdx.y * 128, bn = blockIdx.x * 128;
    const int lr = tid >> 1;          // 0..127 : row within tile for loading
    const int lk = (tid & 1) << 2;    // 0 or 4 : k offset (float4)
    const int tm = (tid >> 4) << 3;   // compute row offset
    const int tn = (tid & 15) << 3;   // compute col offset

    const float* Ap = A + (size_t)(bm + lr) * K + lk;
    const float* Wp = W + (size_t)(bn + lr) * K + lk;

    float acc[8][8] = {};
    for (int k0 = 0; k0 < K; k0 += 8) {
        float4 av = *(const float4*)(Ap + k0);
        float4 bv = *(const float4*)(Wp + k0);
        __syncthreads();
        As[lk+0][lr]=av.x; As[lk+1][lr]=av.y; As[lk+2][lr]=av.z; As[lk+3][lr]=av.w;
        Bs[lk+0][lr]=bv.x; Bs[lk+1][lr]=bv.y; Bs[lk+2][lr]=bv.z; Bs[lk+3][lr]=bv.w;
        __syncthreads();
        #pragma unroll
        for (int kk = 0; kk < 8; kk++) {
            float a[8], b[8];
            *(float4*)&a[0] = *(const float4*)&As[kk][tm];
            *(float4*)&a[4] = *(const float4*)&As[kk][tm+4];
            *(float4*)&b[0] = *(const float4*)&Bs[kk][tn];
            *(float4*)&b[4] = *(const float4*)&Bs[kk][tn+4];
            #pragma unroll
            for (int i = 0; i < 8; i++)
                #pragma unroll
                for (int j = 0; j < 8; j++)
                    acc[i][j] = fmaf(a[i], b[j], acc[i][j]);
        }
    }

    const int n0 = bn + tn;                  // 8 consecutive cols (within one head chunk)
    const float b0 = bias[n0+0], b1 = bias[n0+1], b2 = bias[n0+2], b3 = bias[n0+3];
    const float b4 = bias[n0+4], b5 = bias[n0+5], b6 = bias[n0+6], b7 = bias[n0+7];
    #pragma unroll
    for (int i = 0; i < 8; i++) {
        const int row = bm + tm + i;
        float4 v0 = make_float4(acc[i][0]+b0, acc[i][1]+b1, acc[i][2]+b2, acc[i][3]+b3);
        float4 v1 = make_float4(acc[i][4]+b4, acc[i][5]+b5, acc[i][6]+b6, acc[i][7]+b7);
        if (MODE == 0) {
            const int b  = row >> 11;        // row / 2048
            const int s  = row & 2047;
            const int hd = n0 >> 7;          // head
            const int dd = n0 & 127;
            float* dst = out + ((size_t)(b*NH + hd) * S_ + s) * HD + dd;
            *(float4*)(dst)     = v0;
            *(float4*)(dst + 4) = v1;
        } else {
            float* dst = out + (size_t)row * H_ + n0;
            *(float4*)(dst)     = v0;
            *(float4*)(dst + 4) = v1;
        }
    }
}

// ---------------------------------------------------------------------------
// Flash attention, causal. One block = (b,h) x 64 q-rows. 256 threads (16x16).
// Thread (ty,tx): scores 4x4 (rows ty*4.., cols tx*4..), output 4x(4+4)
// (cols tx*4.. and 64+tx*4..). smem: Q^T, K^T (stride 68), V (stride 128),
// P (stride 68). Online softmax in registers, row reductions via shfl over tx.
// ---------------------------------------------------------------------------
#define QT_OFF 0
#define KT_OFF 8704
#define VS_OFF 17408
#define PS_OFF 25600
#define FLASH_SMEM_FLOATS 29952   // *4 = 119808 bytes

__global__ __launch_bounds__(256) void flash_attn(
    const float* __restrict__ Q, const float* __restrict__ K,
    const float* __restrict__ V, float* __restrict__ ctx)
{
    extern __shared__ float sm[];
    const int tid = threadIdx.x;
    const int ty = tid >> 4, tx = tid & 15;
    const int ty4 = ty << 2, tx4 = tx << 2;
    const int bh = blockIdx.y;             // b*16 + head
    const int b  = bh >> 4, head = bh & 15;
    const int q0 = blockIdx.x << 6;
    const size_t base = (size_t)bh * S_ * HD;
    const float scale = 0.08838834764831845f;   // 1/sqrt(128)

    // Load Q tile transposed: Qt[d][r], stride 68
    {
        const float* Qg = Q + base + (size_t)q0 * HD;
        for (int it = tid; it < 2048; it += 256) {
            int r  = it >> 5;
            int c4 = (it & 31) << 2;
            float4 v = *(const float4*)(Qg + r*HD + c4);
            sm[QT_OFF + (c4+0)*68 + r] = v.x;
            sm[QT_OFF + (c4+1)*68 + r] = v.y;
            sm[QT_OFF + (c4+2)*68 + r] = v.z;
            sm[QT_OFF + (c4+3)*68 + r] = v.w;
        }
    }

    float acc[4][8] = {};
    float mrow[4] = {-3e38f, -3e38f, -3e38f, -3e38f};
    float lrow[4] = {};

    const int ntiles = blockIdx.x + 1;
    for (int kt = 0; kt < ntiles; kt++) {
        const int k0 = kt << 6;
        const bool diag = (k0 == q0);
        __syncthreads();   // previous Kt/Vs/Ps consumers done (also covers Q-load on iter 0)
        // Load K tile transposed + V tile straight
        {
            const float* Kg = K + base + (size_t)k0 * HD;
            const float* Vg = V + base + (size_t)k0 * HD;
            for (int it = tid; it < 2048; it += 256) {
                int r  = it >> 5;
                int c4 = (it & 31) << 2;
                float4 v = *(const float4*)(Kg + r*HD + c4);
                sm[KT_OFF + (c4+0)*68 + r] = v.x;
                sm[KT_OFF + (c4+1)*68 + r] = v.y;
                sm[KT_OFF + (c4+2)*68 + r] = v.z;
                sm[KT_OFF + (c4+3)*68 + r] = v.w;
                ((float4*)(sm + VS_OFF))[it] = ((const float4*)Vg)[it];
            }
        }
        __syncthreads();

        // S = Q K^T  (4x4 per thread)
        float s[4][4] = {};
        #pragma unroll 8
        for (int kk = 0; kk < 128; kk++) {
            float4 a = *(const float4*)&sm[QT_OFF + kk*68 + ty4];
            float4 c = *(const float4*)&sm[KT_OFF + kk*68 + tx4];
            const float af[4] = {a.x, a.y, a.z, a.w};
            const float cf[4] = {c.x, c.y, c.z, c.w};
            #pragma unroll
            for (int i = 0; i < 4; i++)
                #pragma unroll
                for (int j = 0; j < 4; j++)
                    s[i][j] = fmaf(af[i], cf[j], s[i][j]);
        }

        // Online softmax per owned row; write P to smem
        #pragma unroll
        for (int i = 0; i < 4; i++) {
            float vv[4];
            float vmax = -3e38f;
            const int row = q0 + ty4 + i;
            #pragma unroll
            for (int j = 0; j < 4; j++) {
                float val = s[i][j] * scale;
                if (diag && (k0 + tx4 + j > row)) val = -1e30f;
                vv[j] = val;
                vmax = fmaxf(vmax, val);
            }
            vmax = fmaxf(vmax, __shfl_xor_sync(0xffffffffu, vmax, 1));
            vmax = fmaxf(vmax, __shfl_xor_sync(0xffffffffu, vmax, 2));
            vmax = fmaxf(vmax, __shfl_xor_sync(0xffffffffu, vmax, 4));
            vmax = fmaxf(vmax, __shfl_xor_sync(0xffffffffu, vmax, 8));
            const float mnew = fmaxf(mrow[i], vmax);
            const float corr = __expf(mrow[i] - mnew);
            float rsum = 0.f;
            #pragma unroll
            for (int j = 0; j < 4; j++) {
                float p = __expf(vv[j] - mnew);
                sm[PS_OFF + (ty4+i)*68 + tx4 + j] = p;
                rsum += p;
            }
            rsum += __shfl_xor_sync(0xffffffffu, rsum, 1);
            rsum += __shfl_xor_sync(0xffffffffu, rsum, 2);
            rsum += __shfl_xor_sync(0xffffffffu, rsum, 4);
            rsum += __shfl_xor_sync(0xffffffffu, rsum, 8);
            lrow[i] = lrow[i] * corr + rsum;
            mrow[i] = mnew;
            #pragma unroll
            for (int j = 0; j < 8; j++) acc[i][j] *= corr;
        }
        __syncthreads();

        // O += P V  (rows ty4.., cols tx4.. and 64+tx4..)
        #pragma unroll 4
        for (int kk = 0; kk < 64; kk++) {
            float4 v0 = *(const float4*)&sm[VS_OFF + kk*128 + tx4];
            float4 v1 = *(const float4*)&sm[VS_OFF + kk*128 + 64 + tx4];
            const float vf[8] = {v0.x, v0.y, v0.z, v0.w, v1.x, v1.y, v1.z, v1.w};
            #pragma unroll
            for (int i = 0; i < 4; i++) {
                const float p = sm[PS_OFF + (ty4+i)*68 + kk];
                #pragma unroll
                for (int j = 0; j < 8; j++)
                    acc[i][j] = fmaf(p, vf[j], acc[i][j]);
            }
        }
    }

    // Epilogue: O /= l, write ctx in [b,s,h] layout
    #pragma unroll
    for (int i = 0; i < 4; i++) {
        const float inv = 1.f / lrow[i];
        const int row = q0 + ty4 + i;
        float* dst = ctx + ((size_t)b * S_ + row) * H_ + head * HD;
        float4 o0 = make_float4(acc[i][0]*inv, acc[i][1]*inv, acc[i][2]*inv, acc[i][3]*inv);
        float4 o1 = make_float4(acc[i][4]*inv, acc[i][5]*inv, acc[i][6]*inv, acc[i][7]*inv);
        *(float4*)(dst + tx4)      = o0;
        *(float4*)(dst + 64 + tx4) = o1;
    }
}

// ---------------------------------------------------------------------------
extern "C" void kernel_launch(void* const* d_in, const int* in_sizes, int n_in,
                              void* d_out, int out_size)
{
    const float* x  = (const float*)d_in[0];
    const float* wq = (const float*)d_in[1];
    const float* bq = (const float*)d_in[2];
    const float* wk = (const float*)d_in[3];
    const float* bk = (const float*)d_in[4];
    const float* wv = (const float*)d_in[5];
    const float* bv = (const float*)d_in[6];
    const float* wo = (const float*)d_in[7];
    const float* bo = (const float*)d_in[8];
    float* out = (float*)d_out;

    float *q, *k, *v, *ctx;
    cudaGetSymbolAddress((void**)&q,   g_q);
    cudaGetSymbolAddress((void**)&k,   g_k);
    cudaGetSymbolAddress((void**)&v,   g_v);
    cudaGetSymbolAddress((void**)&ctx, g_ctx);

    static bool attr_set = false;
    if (!attr_set) {
        cudaFuncSetAttribute(flash_attn, cudaFuncAttributeMaxDynamicSharedMemorySize,
                             FLASH_SMEM_FLOATS * 4);
        attr_set = true;
    }

    dim3 gg(H_/128, M_/128);    // (16, 32)
    sgemm_nt<0><<<gg, 256>>>(x, wq, bq, q);
    sgemm_nt<0><<<gg, 256>>>(x, wk, bk, k);
    sgemm_nt<0><<<gg, 256>>>(x, wv, bv, v);

    dim3 gf(S_/64, B_*NH);      // (32, 32)
    flash_attn<<<gf, 256, FLASH_SMEM_FLOATS * 4>>>(q, k, v, ctx);

    sgemm_nt<1><<<gg, 256>>>(ctx, wo, bo, out);
}

// round 3
// speedup vs baseline: 2.7642x; 2.7642x over previous
#include <cuda_runtime.h>
#include <cuda_bf16.h>
#include <cstdint>

#define B_  2
#define S_  2048
#define H_  2048
#define NH  16
#define HD  128
#define M_  (B_*S_)

// Single shared-memory symbol for the whole TU (extern __shared__ is TU-global)
extern __shared__ __align__(16) unsigned char sm_raw[];

// ---------------------------------------------------------------------------
// Scratch (static device allocations are allowed; cudaMalloc is not)
// ---------------------------------------------------------------------------
__device__ float g_q[(size_t)B_*NH*S_*HD];    // [b,h,s,d]
__device__ float g_k[(size_t)B_*NH*S_*HD];
__device__ float g_v[(size_t)B_*NH*S_*HD];
__device__ float g_ctx[(size_t)B_*S_*H_];     // [b,s,h]

__device__ __nv_bfloat16 g_xhi[(size_t)M_*H_];
__device__ __nv_bfloat16 g_xlo[(size_t)M_*H_];
__device__ __nv_bfloat16 g_whi[4][(size_t)H_*H_];
__device__ __nv_bfloat16 g_wlo[4][(size_t)H_*H_];
__device__ __nv_bfloat16 g_chi[(size_t)M_*H_];
__device__ __nv_bfloat16 g_clo[(size_t)M_*H_];

// ---------------------------------------------------------------------------
// fp32 -> (hi, lo) bf16 split.  v ~= hi + lo with ~16 mantissa bits kept.
// ---------------------------------------------------------------------------
__global__ void split_bf16(const float* __restrict__ in,
                           __nv_bfloat16* __restrict__ hi,
                           __nv_bfloat16* __restrict__ lo, int n4)
{
    int i = blockIdx.x * blockDim.x + threadIdx.x;
    int stride = gridDim.x * blockDim.x;
    for (; i < n4; i += stride) {
        float4 v = ((const float4*)in)[i];
        __nv_bfloat16 h0 = __float2bfloat16(v.x);
        __nv_bfloat16 h1 = __float2bfloat16(v.y);
        __nv_bfloat16 h2 = __float2bfloat16(v.z);
        __nv_bfloat16 h3 = __float2bfloat16(v.w);
        __nv_bfloat162* hp = (__nv_bfloat162*)hi;
        __nv_bfloat162* lp = (__nv_bfloat162*)lo;
        hp[2*i+0] = __nv_bfloat162(h0, h1);
        hp[2*i+1] = __nv_bfloat162(h2, h3);
        lp[2*i+0] = __nv_bfloat162(__float2bfloat16(v.x - __bfloat162float(h0)),
                                   __float2bfloat16(v.y - __bfloat162float(h1)));
        lp[2*i+1] = __nv_bfloat162(__float2bfloat16(v.z - __bfloat162float(h2)),
                                   __float2bfloat16(v.w - __bfloat162float(h3)));
    }
}

// ---------------------------------------------------------------------------
// PTX helpers
// ---------------------------------------------------------------------------
__device__ __forceinline__ uint32_t smem_u32(const void* p) {
    uint32_t a;
    asm("{ .reg .u64 t; cvta.to.shared.u64 t, %1; cvt.u32.u64 %0, t; }" : "=r"(a) : "l"(p));
    return a;
}
__device__ __forceinline__ void cp16(uint32_t s, const void* g) {
    asm volatile("cp.async.cg.shared.global [%0], [%1], 16;\n" :: "r"(s), "l"(g));
}
__device__ __forceinline__ void cp_commit() { asm volatile("cp.async.commit_group;\n"); }
template<int N> __device__ __forceinline__ void cp_wait() {
    asm volatile("cp.async.wait_group %0;\n" :: "n"(N));
}
__device__ __forceinline__ void mma16816(float* d, const uint32_t* a, const uint32_t* b) {
    asm volatile("mma.sync.aligned.m16n8k16.row.col.f32.bf16.bf16.f32 "
                 "{%0,%1,%2,%3}, {%4,%5,%6,%7}, {%8,%9}, {%0,%1,%2,%3};\n"
                 : "+f"(d[0]), "+f"(d[1]), "+f"(d[2]), "+f"(d[3])
                 : "r"(a[0]), "r"(a[1]), "r"(a[2]), "r"(a[3]), "r"(b[0]), "r"(b[1]));
}

// ---------------------------------------------------------------------------
// bf16x3 GEMM (NT): C[M,N] = A[M,K] * W[N,K]^T + bias
//   A,W given as (hi,lo) bf16 pairs; C = Ahi*Bhi + Ahi*Blo + Alo*Bhi (fp32 acc)
// BM=BN=128, BK=32, 256 threads (8 warps, 2x4), warp tile 64x32, mma m16n8k16.
// smem stride 40 bf16 (80B) -> conflict-free fragment loads, 16B-aligned cp.async.
// MODE 0: scatter to [b,head,s,d].  MODE 1: plain [M,N].
// ---------------------------------------------------------------------------
#define GSTRIDE 40
#define TILE_ELEMS (128*GSTRIDE)          // 5120 bf16 per operand tile
#define STAGE_ELEMS (4*TILE_ELEMS)        // Ahi,Alo,Whi,Wlo
#define GEMM_SMEM_BYTES (2*STAGE_ELEMS*2) // 81920

template<int MODE>
__global__ __launch_bounds__(256) void gemm_bf16x3(
    const __nv_bfloat16* __restrict__ Ahi, const __nv_bfloat16* __restrict__ Alo,
    const __nv_bfloat16* __restrict__ Whi, const __nv_bfloat16* __restrict__ Wlo,
    const float* __restrict__ bias, float* __restrict__ out)
{
    __nv_bfloat16* sm = (__nv_bfloat16*)sm_raw;
    const int K = H_;
    const int tid  = threadIdx.x;
    const int lane = tid & 31, warp = tid >> 5;
    const int g = lane >> 2, tg = lane & 3;
    const int wm = (warp >> 2) * 64, wn = (warp & 3) * 32;
    const int bm = blockIdx.y * 128, bn = blockIdx.x * 128;

    const uint32_t sbase = smem_u32(sm);

    // loader: each thread fills 2 chunks of 16B per operand tile
    const int lrow0 = tid >> 2;          // rows for chunk 0 (0..63) / chunk1 (+64)
    const int lc8   = (tid & 3) * 8;     // col offset in bf16
    const __nv_bfloat16* gA = Ahi + (size_t)(bm + lrow0) * K + lc8;
    const __nv_bfloat16* gAl= Alo + (size_t)(bm + lrow0) * K + lc8;
    const __nv_bfloat16* gW = Whi + (size_t)(bn + lrow0) * K + lc8;
    const __nv_bfloat16* gWl= Wlo + (size_t)(bn + lrow0) * K + lc8;
    const uint32_t soff0 = (uint32_t)(lrow0 * GSTRIDE + lc8) * 2;
    const uint32_t srowadd = 64 * GSTRIDE * 2;

    auto issue = [&](int kt, int buf) {
        const int k0 = kt * 32;
        uint32_t sb = sbase + buf * (STAGE_ELEMS * 2);
        #pragma unroll
        for (int t = 0; t < 2; t++) {
            uint32_t so = soff0 + t * srowadd;
            size_t go = (size_t)t * 64 * K + k0;
            cp16(sb + 0*TILE_ELEMS*2 + so, gA  + go);
            cp16(sb + 1*TILE_ELEMS*2 + so, gAl + go);
            cp16(sb + 2*TILE_ELEMS*2 + so, gW  + go);
            cp16(sb + 3*TILE_ELEMS*2 + so, gWl + go);
        }
        cp_commit();
    };

    float acc[4][4][4] = {};

    issue(0, 0);
    issue(1, 1);

    const int NT = K / 32;   // 64
    for (int kt = 0; kt < NT; kt++) {
        if (kt < NT - 1) cp_wait<1>(); else cp_wait<0>();
        __syncthreads();

        const __nv_bfloat16* As  = sm + (kt & 1) * STAGE_ELEMS;
        const __nv_bfloat16* Als = As + TILE_ELEMS;
        const __nv_bfloat16* Bs  = As + 2 * TILE_ELEMS;
        const __nv_bfloat16* Bls = As + 3 * TILE_ELEMS;

        #pragma unroll
        for (int kh = 0; kh < 32; kh += 16) {
            const int ac = kh + 2 * tg;
            uint32_t af[4][4], bh[4][2], bl[4][2];
            #pragma unroll
            for (int mi = 0; mi < 4; mi++) {
                const int r = (wm + mi * 16 + g) * GSTRIDE + ac;
                af[mi][0] = *(const uint32_t*)&As[r];
                af[mi][1] = *(const uint32_t*)&As[r + 8 * GSTRIDE];
                af[mi][2] = *(const uint32_t*)&As[r + 8];
                af[mi][3] = *(const uint32_t*)&As[r + 8 * GSTRIDE + 8];
            }
            #pragma unroll
            for (int ni = 0; ni < 4; ni++) {
                const int r = (wn + ni * 8 + g) * GSTRIDE + ac;
                bh[ni][0] = *(const uint32_t*)&Bs[r];
                bh[ni][1] = *(const uint32_t*)&Bs[r + 8];
            }
            #pragma unroll
            for (int mi = 0; mi < 4; mi++)
                #pragma unroll
                for (int ni = 0; ni < 4; ni++)
                    mma16816(acc[mi][ni], af[mi], bh[ni]);       // hi*hi
            #pragma unroll
            for (int ni = 0; ni < 4; ni++) {
                const int r = (wn + ni * 8 + g) * GSTRIDE + ac;
                bl[ni][0] = *(const uint32_t*)&Bls[r];
                bl[ni][1] = *(const uint32_t*)&Bls[r + 8];
            }
            #pragma unroll
            for (int mi = 0; mi < 4; mi++)
                #pragma unroll
                for (int ni = 0; ni < 4; ni++)
                    mma16816(acc[mi][ni], af[mi], bl[ni]);       // hi*lo
            #pragma unroll
            for (int mi = 0; mi < 4; mi++) {
                const int r = (wm + mi * 16 + g) * GSTRIDE + ac;
                af[mi][0] = *(const uint32_t*)&Als[r];
                af[mi][1] = *(const uint32_t*)&Als[r + 8 * GSTRIDE];
                af[mi][2] = *(const uint32_t*)&Als[r + 8];
                af[mi][3] = *(const uint32_t*)&Als[r + 8 * GSTRIDE + 8];
            }
            #pragma unroll
            for (int mi = 0; mi < 4; mi++)
                #pragma unroll
                for (int ni = 0; ni < 4; ni++)
                    mma16816(acc[mi][ni], af[mi], bh[ni]);       // lo*hi
        }
        __syncthreads();
        if (kt + 2 < NT) issue(kt + 2, kt & 1);
    }

    // epilogue
    #pragma unroll
    for (int ni = 0; ni < 4; ni++) {
        const int n0 = bn + wn + ni * 8 + 2 * tg;
        const float b0 = bias[n0], b1 = bias[n0 + 1];
        #pragma unroll
        for (int mi = 0; mi < 4; mi++) {
            #pragma unroll
            for (int h = 0; h < 2; h++) {
                const int row = bm + wm + mi * 16 + g + h * 8;
                float2 v = make_float2(acc[mi][ni][2*h+0] + b0, acc[mi][ni][2*h+1] + b1);
                if (MODE == 0) {
                    const int b  = row >> 11;
                    const int s  = row & 2047;
                    const int hd = n0 >> 7;
                    const int dd = n0 & 127;
                    *(float2*)(out + ((size_t)(b * NH + hd) * S_ + s) * HD + dd) = v;
                } else {
                    *(float2*)(out + (size_t)row * H_ + n0) = v;
                }
            }
        }
    }
}

// ---------------------------------------------------------------------------
// Flash attention (fp32 SIMT, unchanged from R1)
// ---------------------------------------------------------------------------
#define QT_OFF 0
#define KT_OFF 8704
#define VS_OFF 17408
#define PS_OFF 25600
#define FLASH_SMEM_FLOATS 29952

__global__ __launch_bounds__(256) void flash_attn(
    const float* __restrict__ Q, const float* __restrict__ K,
    const float* __restrict__ V, float* __restrict__ ctx)
{
    float* sm = (float*)sm_raw;
    const int tid = threadIdx.x;
    const int ty = tid >> 4, tx = tid & 15;
    const int ty4 = ty << 2, tx4 = tx << 2;
    const int bh = blockIdx.y;
    const int b  = bh >> 4, head = bh & 15;
    const int q0 = blockIdx.x << 6;
    const size_t base = (size_t)bh * S_ * HD;
    const float scale = 0.08838834764831845f;

    {
        const float* Qg = Q + base + (size_t)q0 * HD;
        for (int it = tid; it < 2048; it += 256) {
            int r  = it >> 5;
            int c4 = (it & 31) << 2;
            float4 v = *(const float4*)(Qg + r*HD + c4);
            sm[QT_OFF + (c4+0)*68 + r] = v.x;
            sm[QT_OFF + (c4+1)*68 + r] = v.y;
            sm[QT_OFF + (c4+2)*68 + r] = v.z;
            sm[QT_OFF + (c4+3)*68 + r] = v.w;
        }
    }

    float acc[4][8] = {};
    float mrow[4] = {-3e38f, -3e38f, -3e38f, -3e38f};
    float lrow[4] = {};

    const int ntiles = blockIdx.x + 1;
    for (int kt = 0; kt < ntiles; kt++) {
        const int k0 = kt << 6;
        const bool diag = (k0 == q0);
        __syncthreads();
        {
            const float* Kg = K + base + (size_t)k0 * HD;
            const float* Vg = V + base + (size_t)k0 * HD;
            for (int it = tid; it < 2048; it += 256) {
                int r  = it >> 5;
                int c4 = (it & 31) << 2;
                float4 v = *(const float4*)(Kg + r*HD + c4);
                sm[KT_OFF + (c4+0)*68 + r] = v.x;
                sm[KT_OFF + (c4+1)*68 + r] = v.y;
                sm[KT_OFF + (c4+2)*68 + r] = v.z;
                sm[KT_OFF + (c4+3)*68 + r] = v.w;
                ((float4*)(sm + VS_OFF))[it] = ((const float4*)Vg)[it];
            }
        }
        __syncthreads();

        float s[4][4] = {};
        #pragma unroll 8
        for (int kk = 0; kk < 128; kk++) {
            float4 a = *(const float4*)&sm[QT_OFF + kk*68 + ty4];
            float4 c = *(const float4*)&sm[KT_OFF + kk*68 + tx4];
            const float af[4] = {a.x, a.y, a.z, a.w};
            const float cf[4] = {c.x, c.y, c.z, c.w};
            #pragma unroll
            for (int i = 0; i < 4; i++)
                #pragma unroll
                for (int j = 0; j < 4; j++)
                    s[i][j] = fmaf(af[i], cf[j], s[i][j]);
        }

        #pragma unroll
        for (int i = 0; i < 4; i++) {
            float vv[4];
            float vmax = -3e38f;
            const int row = q0 + ty4 + i;
            #pragma unroll
            for (int j = 0; j < 4; j++) {
                float val = s[i][j] * scale;
                if (diag && (k0 + tx4 + j > row)) val = -1e30f;
                vv[j] = val;
                vmax = fmaxf(vmax, val);
            }
            vmax = fmaxf(vmax, __shfl_xor_sync(0xffffffffu, vmax, 1));
            vmax = fmaxf(vmax, __shfl_xor_sync(0xffffffffu, vmax, 2));
            vmax = fmaxf(vmax, __shfl_xor_sync(0xffffffffu, vmax, 4));
            vmax = fmaxf(vmax, __shfl_xor_sync(0xffffffffu, vmax, 8));
            const float mnew = fmaxf(mrow[i], vmax);
            const float corr = __expf(mrow[i] - mnew);
            float rsum = 0.f;
            #pragma unroll
            for (int j = 0; j < 4; j++) {
                float p = __expf(vv[j] - mnew);
                sm[PS_OFF + (ty4+i)*68 + tx4 + j] = p;
                rsum += p;
            }
            rsum += __shfl_xor_sync(0xffffffffu, rsum, 1);
            rsum += __shfl_xor_sync(0xffffffffu, rsum, 2);
            rsum += __shfl_xor_sync(0xffffffffu, rsum, 4);
            rsum += __shfl_xor_sync(0xffffffffu, rsum, 8);
            lrow[i] = lrow[i] * corr + rsum;
            mrow[i] = mnew;
            #pragma unroll
            for (int j = 0; j < 8; j++) acc[i][j] *= corr;
        }
        __syncthreads();

        #pragma unroll 4
        for (int kk = 0; kk < 64; kk++) {
            float4 v0 = *(const float4*)&sm[VS_OFF + kk*128 + tx4];
            float4 v1 = *(const float4*)&sm[VS_OFF + kk*128 + 64 + tx4];
            const float vf[8] = {v0.x, v0.y, v0.z, v0.w, v1.x, v1.y, v1.z, v1.w};
            #pragma unroll
            for (int i = 0; i < 4; i++) {
                const float p = sm[PS_OFF + (ty4+i)*68 + kk];
                #pragma unroll
                for (int j = 0; j < 8; j++)
                    acc[i][j] = fmaf(p, vf[j], acc[i][j]);
            }
        }
    }

    #pragma unroll
    for (int i = 0; i < 4; i++) {
        const float inv = 1.f / lrow[i];
        const int row = q0 + ty4 + i;
        float* dst = ctx + ((size_t)b * S_ + row) * H_ + head * HD;
        float4 o0 = make_float4(acc[i][0]*inv, acc[i][1]*inv, acc[i][2]*inv, acc[i][3]*inv);
        float4 o1 = make_float4(acc[i][4]*inv, acc[i][5]*inv, acc[i][6]*inv, acc[i][7]*inv);
        *(float4*)(dst + tx4)      = o0;
        *(float4*)(dst + 64 + tx4) = o1;
    }
}

// ---------------------------------------------------------------------------
extern "C" void kernel_launch(void* const* d_in, const int* in_sizes, int n_in,
                              void* d_out, int out_size)
{
    const float* x  = (const float*)d_in[0];
    const float* wq = (const float*)d_in[1];
    const float* bq = (const float*)d_in[2];
    const float* wk = (const float*)d_in[3];
    const float* bk = (const float*)d_in[4];
    const float* wv = (const float*)d_in[5];
    const float* bv = (const float*)d_in[6];
    const float* wo = (const float*)d_in[7];
    const float* bo = (const float*)d_in[8];
    float* out = (float*)d_out;

    float *q, *k, *v, *ctx;
    __nv_bfloat16 *xhi, *xlo, *whi, *wlo, *chi, *clo;
    cudaGetSymbolAddress((void**)&q,   g_q);
    cudaGetSymbolAddress((void**)&k,   g_k);
    cudaGetSymbolAddress((void**)&v,   g_v);
    cudaGetSymbolAddress((void**)&ctx, g_ctx);
    cudaGetSymbolAddress((void**)&xhi, g_xhi);
    cudaGetSymbolAddress((void**)&xlo, g_xlo);
    cudaGetSymbolAddress((void**)&whi, g_whi);
    cudaGetSymbolAddress((void**)&wlo, g_wlo);
    cudaGetSymbolAddress((void**)&chi, g_chi);
    cudaGetSymbolAddress((void**)&clo, g_clo);

    static bool attr_set = false;
    if (!attr_set) {
        cudaFuncSetAttribute(flash_attn, cudaFuncAttributeMaxDynamicSharedMemorySize,
                             FLASH_SMEM_FLOATS * 4);
        cudaFuncSetAttribute(gemm_bf16x3<0>, cudaFuncAttributeMaxDynamicSharedMemorySize,
                             GEMM_SMEM_BYTES);
        cudaFuncSetAttribute(gemm_bf16x3<1>, cudaFuncAttributeMaxDynamicSharedMemorySize,
                             GEMM_SMEM_BYTES);
        attr_set = true;
    }

    const size_t WN = (size_t)H_ * H_;
    // splits
    split_bf16<<<1024, 256>>>(x,  xhi, xlo, M_*H_/4);
    split_bf16<<<512,  256>>>(wq, whi + 0*WN, wlo + 0*WN, H_*H_/4);
    split_bf16<<<512,  256>>>(wk, whi + 1*WN, wlo + 1*WN, H_*H_/4);
    split_bf16<<<512,  256>>>(wv, whi + 2*WN, wlo + 2*WN, H_*H_/4);
    split_bf16<<<512,  256>>>(wo, whi + 3*WN, wlo + 3*WN, H_*H_/4);

    dim3 gg(H_/128, M_/128);    // (16, 32)
    gemm_bf16x3<0><<<gg, 256, GEMM_SMEM_BYTES>>>(xhi, xlo, whi + 0*WN, wlo + 0*WN, bq, q);
    gemm_bf16x3<0><<<gg, 256, GEMM_SMEM_BYTES>>>(xhi, xlo, whi + 1*WN, wlo + 1*WN, bk, k);
    gemm_bf16x3<0><<<gg, 256, GEMM_SMEM_BYTES>>>(xhi, xlo, whi + 2*WN, wlo + 2*WN, bv, v);

    dim3 gf(S_/64, B_*NH);      // (32, 32)
    flash_attn<<<gf, 256, FLASH_SMEM_FLOATS * 4>>>(q, k, v, ctx);

    split_bf16<<<1024, 256>>>(ctx, chi, clo, M_*H_/4);
    gemm_bf16x3<1><<<gg, 256, GEMM_SMEM_BYTES>>>(chi, clo, whi + 3*WN, wlo + 3*WN, bo, out);
}

// round 4
// speedup vs baseline: 4.7266x; 1.7099x over previous
#include <cuda_runtime.h>
#include <cuda_bf16.h>
#include <cstdint>

#define B_  2
#define S_  2048
#define H_  2048
#define NH  16
#define HD  128
#define M_  (B_*S_)
#define NQ  (S_/128)

// Single shared-memory symbol for the whole TU
extern __shared__ __align__(16) unsigned char sm_raw[];

// ---------------------------------------------------------------------------
// Scratch
// ---------------------------------------------------------------------------
__device__ __nv_bfloat16 g_xhi[(size_t)M_*H_];
__device__ __nv_bfloat16 g_xlo[(size_t)M_*H_];
__device__ __nv_bfloat16 g_whi[4][(size_t)H_*H_];
__device__ __nv_bfloat16 g_wlo[4][(size_t)H_*H_];
__device__ __nv_bfloat16 g_qhi[(size_t)M_*H_];   // [b,h,s,d], pre-scaled
__device__ __nv_bfloat16 g_qlo[(size_t)M_*H_];
__device__ __nv_bfloat16 g_khi[(size_t)M_*H_];   // [b,h,s,d]
__device__ __nv_bfloat16 g_klo[(size_t)M_*H_];
__device__ __nv_bfloat16 g_vthi[(size_t)M_*H_];  // [b,h,d,s] (transposed)
__device__ __nv_bfloat16 g_vtlo[(size_t)M_*H_];
__device__ __nv_bfloat16 g_chi[(size_t)M_*H_];   // [b,s,h]
__device__ __nv_bfloat16 g_clo[(size_t)M_*H_];

// ---------------------------------------------------------------------------
__global__ void split_bf16(const float* __restrict__ in,
                           __nv_bfloat16* __restrict__ hi,
                           __nv_bfloat16* __restrict__ lo, int n4)
{
    int i = blockIdx.x * blockDim.x + threadIdx.x;
    int stride = gridDim.x * blockDim.x;
    for (; i < n4; i += stride) {
        float4 v = ((const float4*)in)[i];
        __nv_bfloat16 h0 = __float2bfloat16(v.x);
        __nv_bfloat16 h1 = __float2bfloat16(v.y);
        __nv_bfloat16 h2 = __float2bfloat16(v.z);
        __nv_bfloat16 h3 = __float2bfloat16(v.w);
        __nv_bfloat162* hp = (__nv_bfloat162*)hi;
        __nv_bfloat162* lp = (__nv_bfloat162*)lo;
        hp[2*i+0] = __nv_bfloat162(h0, h1);
        hp[2*i+1] = __nv_bfloat162(h2, h3);
        lp[2*i+0] = __nv_bfloat162(__float2bfloat16(v.x - __bfloat162float(h0)),
                                   __float2bfloat16(v.y - __bfloat162float(h1)));
        lp[2*i+1] = __nv_bfloat162(__float2bfloat16(v.z - __bfloat162float(h2)),
                                   __float2bfloat16(v.w - __bfloat162float(h3)));
    }
}

// ---------------------------------------------------------------------------
// PTX helpers
// ---------------------------------------------------------------------------
__device__ __forceinline__ uint32_t smem_u32(const void* p) {
    uint32_t a;
    asm("{ .reg .u64 t; cvta.to.shared.u64 t, %1; cvt.u32.u64 %0, t; }" : "=r"(a) : "l"(p));
    return a;
}
__device__ __forceinline__ void cp16(uint32_t s, const void* g) {
    asm volatile("cp.async.cg.shared.global [%0], [%1], 16;\n" :: "r"(s), "l"(g));
}
__device__ __forceinline__ void cp_commit() { asm volatile("cp.async.commit_group;\n"); }
template<int N> __device__ __forceinline__ void cp_wait() {
    asm volatile("cp.async.wait_group %0;\n" :: "n"(N));
}
__device__ __forceinline__ void mma16816(float* d, const uint32_t* a, const uint32_t* b) {
    asm volatile("mma.sync.aligned.m16n8k16.row.col.f32.bf16.bf16.f32 "
                 "{%0,%1,%2,%3}, {%4,%5,%6,%7}, {%8,%9}, {%0,%1,%2,%3};\n"
                 : "+f"(d[0]), "+f"(d[1]), "+f"(d[2]), "+f"(d[3])
                 : "r"(a[0]), "r"(a[1]), "r"(a[2]), "r"(a[3]), "r"(b[0]), "r"(b[1]));
}
__device__ __forceinline__ uint32_t packbf(float a, float b) {
    __nv_bfloat162 h(__float2bfloat16(a), __float2bfloat16(b));
    return *(uint32_t*)&h;
}

// ---------------------------------------------------------------------------
// bf16x3 GEMM (NT): C = A * W^T + bias.  MODE 0: hi/lo [b,h,s,d] (* scale)
// MODE 1: fp32 [M,N].  MODE 2: hi/lo transposed [b,h,d,s].
// ---------------------------------------------------------------------------
#define GSTRIDE 40
#define TILE_ELEMS (128*GSTRIDE)
#define STAGE_ELEMS (4*TILE_ELEMS)
#define GEMM_SMEM_BYTES (2*STAGE_ELEMS*2)

template<int MODE>
__global__ __launch_bounds__(256) void gemm_bf16x3(
    const __nv_bfloat16* __restrict__ Ahi, const __nv_bfloat16* __restrict__ Alo,
    const __nv_bfloat16* __restrict__ Whi, const __nv_bfloat16* __restrict__ Wlo,
    const float* __restrict__ bias, float scale,
    float* __restrict__ outf,
    __nv_bfloat16* __restrict__ outhi, __nv_bfloat16* __restrict__ outlo)
{
    __nv_bfloat16* sm = (__nv_bfloat16*)sm_raw;
    const int K = H_;
    const int tid  = threadIdx.x;
    const int lane = tid & 31, warp = tid >> 5;
    const int g = lane >> 2, tg = lane & 3;
    const int wm = (warp >> 2) * 64, wn = (warp & 3) * 32;
    const int bm = blockIdx.y * 128, bn = blockIdx.x * 128;

    const uint32_t sbase = smem_u32(sm);
    const int lrow0 = tid >> 2;
    const int lc8   = (tid & 3) * 8;
    const __nv_bfloat16* gA = Ahi + (size_t)(bm + lrow0) * K + lc8;
    const __nv_bfloat16* gAl= Alo + (size_t)(bm + lrow0) * K + lc8;
    const __nv_bfloat16* gW = Whi + (size_t)(bn + lrow0) * K + lc8;
    const __nv_bfloat16* gWl= Wlo + (size_t)(bn + lrow0) * K + lc8;
    const uint32_t soff0 = (uint32_t)(lrow0 * GSTRIDE + lc8) * 2;
    const uint32_t srowadd = 64 * GSTRIDE * 2;

    auto issue = [&](int kt, int buf) {
        const int k0 = kt * 32;
        uint32_t sb = sbase + buf * (STAGE_ELEMS * 2);
        #pragma unroll
        for (int t = 0; t < 2; t++) {
            uint32_t so = soff0 + t * srowadd;
            size_t go = (size_t)t * 64 * K + k0;
            cp16(sb + 0*TILE_ELEMS*2 + so, gA  + go);
            cp16(sb + 1*TILE_ELEMS*2 + so, gAl + go);
            cp16(sb + 2*TILE_ELEMS*2 + so, gW  + go);
            cp16(sb + 3*TILE_ELEMS*2 + so, gWl + go);
        }
        cp_commit();
    };

    float acc[4][4][4] = {};
    issue(0, 0);
    issue(1, 1);

    const int NT = K / 32;
    for (int kt = 0; kt < NT; kt++) {
        if (kt < NT - 1) cp_wait<1>(); else cp_wait<0>();
        __syncthreads();

        const __nv_bfloat16* As  = sm + (kt & 1) * STAGE_ELEMS;
        const __nv_bfloat16* Als = As + TILE_ELEMS;
        const __nv_bfloat16* Bs  = As + 2 * TILE_ELEMS;
        const __nv_bfloat16* Bls = As + 3 * TILE_ELEMS;

        #pragma unroll
        for (int kh = 0; kh < 32; kh += 16) {
            const int ac = kh + 2 * tg;
            uint32_t af[4][4], bh[4][2], bl[4][2];
            #pragma unroll
            for (int mi = 0; mi < 4; mi++) {
                const int r = (wm + mi * 16 + g) * GSTRIDE + ac;
                af[mi][0] = *(const uint32_t*)&As[r];
                af[mi][1] = *(const uint32_t*)&As[r + 8 * GSTRIDE];
                af[mi][2] = *(const uint32_t*)&As[r + 8];
                af[mi][3] = *(const uint32_t*)&As[r + 8 * GSTRIDE + 8];
            }
            #pragma unroll
            for (int ni = 0; ni < 4; ni++) {
                const int r = (wn + ni * 8 + g) * GSTRIDE + ac;
                bh[ni][0] = *(const uint32_t*)&Bs[r];
                bh[ni][1] = *(const uint32_t*)&Bs[r + 8];
            }
            #pragma unroll
            for (int mi = 0; mi < 4; mi++)
                #pragma unroll
                for (int ni = 0; ni < 4; ni++)
                    mma16816(acc[mi][ni], af[mi], bh[ni]);
            #pragma unroll
            for (int ni = 0; ni < 4; ni++) {
                const int r = (wn + ni * 8 + g) * GSTRIDE + ac;
                bl[ni][0] = *(const uint32_t*)&Bls[r];
                bl[ni][1] = *(const uint32_t*)&Bls[r + 8];
            }
            #pragma unroll
            for (int mi = 0; mi < 4; mi++)
                #pragma unroll
                for (int ni = 0; ni < 4; ni++)
                    mma16816(acc[mi][ni], af[mi], bl[ni]);
            #pragma unroll
            for (int mi = 0; mi < 4; mi++) {
                const int r = (wm + mi * 16 + g) * GSTRIDE + ac;
                af[mi][0] = *(const uint32_t*)&Als[r];
                af[mi][1] = *(const uint32_t*)&Als[r + 8 * GSTRIDE];
                af[mi][2] = *(const uint32_t*)&Als[r + 8];
                af[mi][3] = *(const uint32_t*)&Als[r + 8 * GSTRIDE + 8];
            }
            #pragma unroll
            for (int mi = 0; mi < 4; mi++)
                #pragma unroll
                for (int ni = 0; ni < 4; ni++)
                    mma16816(acc[mi][ni], af[mi], bh[ni]);
        }
        __syncthreads();
        if (kt + 2 < NT) issue(kt + 2, kt & 1);
    }

    // epilogue
    #pragma unroll
    for (int ni = 0; ni < 4; ni++) {
        const int n0 = bn + wn + ni * 8 + 2 * tg;
        const float b0 = bias[n0], b1 = bias[n0 + 1];
        #pragma unroll
        for (int mi = 0; mi < 4; mi++) {
            #pragma unroll
            for (int h = 0; h < 2; h++) {
                const int row = bm + wm + mi * 16 + g + h * 8;
                float vx = acc[mi][ni][2*h+0] + b0;
                float vy = acc[mi][ni][2*h+1] + b1;
                if (MODE == 1) {
                    *(float2*)(outf + (size_t)row * H_ + n0) = make_float2(vx, vy);
                } else {
                    if (MODE == 0) { vx *= scale; vy *= scale; }
                    __nv_bfloat16 hx = __float2bfloat16(vx);
                    __nv_bfloat16 hy = __float2bfloat16(vy);
                    __nv_bfloat16 lx = __float2bfloat16(vx - __bfloat162float(hx));
                    __nv_bfloat16 ly = __float2bfloat16(vy - __bfloat162float(hy));
                    const int b  = row >> 11;
                    const int s  = row & 2047;
                    const int hd = n0 >> 7;
                    const int dd = n0 & 127;
                    if (MODE == 0) {
                        size_t idx = ((size_t)(b * NH + hd) * S_ + s) * HD + dd;
                        __nv_bfloat162 vh(hx, hy), vl(lx, ly);
                        *(__nv_bfloat162*)(outhi + idx) = vh;
                        *(__nv_bfloat162*)(outlo + idx) = vl;
                    } else { // MODE 2: transposed [b,h,d,s]
                        size_t idx = ((size_t)(b * NH + hd) * HD + dd) * S_ + s;
                        outhi[idx]      = hx;  outhi[idx + S_] = hy;
                        outlo[idx]      = lx;  outlo[idx + S_] = ly;
                    }
                }
            }
        }
    }
}

// ---------------------------------------------------------------------------
// Flash attention, bf16x3 tensor-core. BR=128, BC=64, 256 threads (8 warps).
// Warp w owns rows q0+w*16 .. +15. Double-buffered K/V via cp.async.
// smem (bf16 elems): Q hi/lo @0/17408 (stride 136); K stage @34816+st*17408
// (hi, lo@+8704; stride 136); VT stage @69632+st*18432 (hi, lo@+9216; stride 72).
// ---------------------------------------------------------------------------
#define FL_QHI 0
#define FL_QLO 17408
#define FL_KOF(st)  (34816 + (st)*17408)
#define FL_VOF(st)  (69632 + (st)*18432)
#define FL_SMEM_BYTES (106496*2)

__global__ __launch_bounds__(256, 1) void flash_attn_bf16(
    const __nv_bfloat16* __restrict__ Qhi, const __nv_bfloat16* __restrict__ Qlo,
    const __nv_bfloat16* __restrict__ Khi, const __nv_bfloat16* __restrict__ Klo,
    const __nv_bfloat16* __restrict__ VThi, const __nv_bfloat16* __restrict__ VTlo,
    __nv_bfloat16* __restrict__ Chi, __nv_bfloat16* __restrict__ Clo)
{
    __nv_bfloat16* sm = (__nv_bfloat16*)sm_raw;
    const int tid = threadIdx.x, lane = tid & 31, w = tid >> 5;
    const int g = lane >> 2, tg = lane & 3;
    const int bh = blockIdx.y, b = bh >> 4, head = bh & 15;
    const int q0 = (NQ - 1 - (int)blockIdx.x) * 128;   // heavy blocks first
    const size_t base  = (size_t)bh * S_ * HD;   // Q,K [b,h,s,d]
    const size_t vbase = (size_t)bh * HD * S_;   // VT  [b,h,d,s]
    const uint32_t sb = smem_u32(sm);
    const int ntiles = q0 / 64 + 2;

    auto issueKV = [&](int kt, int st) {
        const int k0 = kt * 64;
        const uint32_t kb = sb + FL_KOF(st) * 2;
        const uint32_t vb = sb + FL_VOF(st) * 2;
        #pragma unroll
        for (int p = 0; p < 4; p++) {
            const int ch = tid + p * 256;
            const int r = ch >> 4, c8 = (ch & 15) * 8;
            cp16(kb + (uint32_t)(r*136 + c8)*2,          Khi + base + (size_t)(k0+r)*HD + c8);
            cp16(kb + (uint32_t)(8704 + r*136 + c8)*2,   Klo + base + (size_t)(k0+r)*HD + c8);
            const int d = ch >> 3, s8 = (ch & 7) * 8;
            cp16(vb + (uint32_t)(d*72 + s8)*2,           VThi + vbase + (size_t)d*S_ + k0 + s8);
            cp16(vb + (uint32_t)(9216 + d*72 + s8)*2,    VTlo + vbase + (size_t)d*S_ + k0 + s8);
        }
        cp_commit();
    };

    issueKV(0, 0);

    // Q tile -> smem (hi, lo)
    #pragma unroll
    for (int p = 0; p < 8; p++) {
        const int ch = tid + p * 256;
        const int r = ch >> 4, c8 = (ch & 15) * 8;
        *(uint4*)(sm + FL_QHI + r*136 + c8) = *(const uint4*)(Qhi + base + (size_t)(q0+r)*HD + c8);
        *(uint4*)(sm + FL_QLO + r*136 + c8) = *(const uint4*)(Qlo + base + (size_t)(q0+r)*HD + c8);
    }

    float oacc[16][4] = {};
    float m0 = -1e30f, m1 = -1e30f, l0 = 0.f, l1 = 0.f;
    const int r0 = q0 + w * 16 + g;

    for (int kt = 0; kt < ntiles; kt++) {
        const int st = kt & 1;
        __syncthreads();                       // all warps done with buf st^1
        if (kt + 1 < ntiles) { issueKV(kt + 1, st ^ 1); cp_wait<1>(); }
        else                 { cp_wait<0>(); }
        __syncthreads();                       // stage st data visible

        // ---- S = Q K^T (bf16x3) ----
        float sacc[8][4];
        #pragma unroll
        for (int j = 0; j < 8; j++)
            sacc[j][0] = sacc[j][1] = sacc[j][2] = sacc[j][3] = 0.f;
        const __nv_bfloat16* Ksm = sm + FL_KOF(st);
        #pragma unroll
        for (int kk = 0; kk < 8; kk++) {
            const int ac = kk * 16 + 2 * tg;
            const int ar = (w * 16 + g) * 136 + ac;
            uint32_t ah[4], al[4], bhh[8][2], bll[8][2];
            ah[0] = *(const uint32_t*)&sm[FL_QHI + ar];
            ah[1] = *(const uint32_t*)&sm[FL_QHI + ar + 8*136];
            ah[2] = *(const uint32_t*)&sm[FL_QHI + ar + 8];
            ah[3] = *(const uint32_t*)&sm[FL_QHI + ar + 8*136 + 8];
            #pragma unroll
            for (int j = 0; j < 8; j++) {
                const int br = (j * 8 + g) * 136 + ac;
                bhh[j][0] = *(const uint32_t*)&Ksm[br];
                bhh[j][1] = *(const uint32_t*)&Ksm[br + 8];
            }
            #pragma unroll
            for (int j = 0; j < 8; j++) mma16816(sacc[j], ah, bhh[j]);
            #pragma unroll
            for (int j = 0; j < 8; j++) {
                const int br = 8704 + (j * 8 + g) * 136 + ac;
                bll[j][0] = *(const uint32_t*)&Ksm[br];
                bll[j][1] = *(const uint32_t*)&Ksm[br + 8];
            }
            #pragma unroll
            for (int j = 0; j < 8; j++) mma16816(sacc[j], ah, bll[j]);
            al[0] = *(const uint32_t*)&sm[FL_QLO + ar];
            al[1] = *(const uint32_t*)&sm[FL_QLO + ar + 8*136];
            al[2] = *(const uint32_t*)&sm[FL_QLO + ar + 8];
            al[3] = *(const uint32_t*)&sm[FL_QLO + ar + 8*136 + 8];
            #pragma unroll
            for (int j = 0; j < 8; j++) mma16816(sacc[j], al, bhh[j]);
        }

        // ---- causal mask ----
        const int k0 = kt * 64;
        if (k0 + 63 > r0) {
            #pragma unroll
            for (int j = 0; j < 8; j++) {
                const int c = k0 + j * 8 + 2 * tg;
                if (c     > r0)     sacc[j][0] = -1e30f;
                if (c + 1 > r0)     sacc[j][1] = -1e30f;
                if (c     > r0 + 8) sacc[j][2] = -1e30f;
                if (c + 1 > r0 + 8) sacc[j][3] = -1e30f;
            }
        }

        // ---- online softmax ----
        float rx0 = -1e30f, rx1 = -1e30f;
        #pragma unroll
        for (int j = 0; j < 8; j++) {
            rx0 = fmaxf(rx0, fmaxf(sacc[j][0], sacc[j][1]));
            rx1 = fmaxf(rx1, fmaxf(sacc[j][2], sacc[j][3]));
        }
        rx0 = fmaxf(rx0, __shfl_xor_sync(0xffffffffu, rx0, 1));
        rx0 = fmaxf(rx0, __shfl_xor_sync(0xffffffffu, rx0, 2));
        rx1 = fmaxf(rx1, __shfl_xor_sync(0xffffffffu, rx1, 1));
        rx1 = fmaxf(rx1, __shfl_xor_sync(0xffffffffu, rx1, 2));
        const float mn0 = fmaxf(m0, rx0), mn1 = fmaxf(m1, rx1);
        const float c0 = __expf(m0 - mn0), c1 = __expf(m1 - mn1);

        uint32_t ph0[8], ph1[8], pl0[8], pl1[8];
        float sum0 = 0.f, sum1 = 0.f;
        #pragma unroll
        for (int j = 0; j < 8; j++) {
            float p00 = __expf(sacc[j][0] - mn0);
            float p01 = __expf(sacc[j][1] - mn0);
            float p10 = __expf(sacc[j][2] - mn1);
            float p11 = __expf(sacc[j][3] - mn1);
            sum0 += p00 + p01;  sum1 += p10 + p11;
            ph0[j] = packbf(p00, p01);
            ph1[j] = packbf(p10, p11);
            __nv_bfloat162 h0 = *(__nv_bfloat162*)&ph0[j];
            __nv_bfloat162 h1 = *(__nv_bfloat162*)&ph1[j];
            pl0[j] = packbf(p00 - __bfloat162float(h0.x), p01 - __bfloat162float(h0.y));
            pl1[j] = packbf(p10 - __bfloat162float(h1.x), p11 - __bfloat162float(h1.y));
        }
        sum0 += __shfl_xor_sync(0xffffffffu, sum0, 1);
        sum0 += __shfl_xor_sync(0xffffffffu, sum0, 2);
        sum1 += __shfl_xor_sync(0xffffffffu, sum1, 1);
        sum1 += __shfl_xor_sync(0xffffffffu, sum1, 2);
        l0 = l0 * c0 + sum0;  m0 = mn0;
        l1 = l1 * c1 + sum1;  m1 = mn1;
        #pragma unroll
        for (int jd = 0; jd < 16; jd++) {
            oacc[jd][0] *= c0; oacc[jd][1] *= c0;
            oacc[jd][2] *= c1; oacc[jd][3] *= c1;
        }

        // ---- O += P V (bf16x3; P from registers) ----
        const __nv_bfloat16* Vsm = sm + FL_VOF(st);
        #pragma unroll
        for (int kk = 0; kk < 4; kk++) {
            uint32_t a_h[4] = { ph0[2*kk], ph1[2*kk], ph0[2*kk+1], ph1[2*kk+1] };
            uint32_t a_l[4] = { pl0[2*kk], pl1[2*kk], pl0[2*kk+1], pl1[2*kk+1] };
            const int ac = kk * 16 + 2 * tg;
            #pragma unroll
            for (int jd = 0; jd < 16; jd++) {
                const int br = (jd * 8 + g) * 72 + ac;
                uint32_t bhv[2] = { *(const uint32_t*)&Vsm[br],
                                    *(const uint32_t*)&Vsm[br + 8] };
                mma16816(oacc[jd], a_h, bhv);
                mma16816(oacc[jd], a_l, bhv);
                uint32_t blv[2] = { *(const uint32_t*)&Vsm[9216 + br],
                                    *(const uint32_t*)&Vsm[9216 + br + 8] };
                mma16816(oacc[jd], a_h, blv);
            }
        }
    }

    // ---- epilogue: normalize, hi/lo bf16, write ctx [b,s,h] ----
    const float i0 = 1.f / l0, i1 = 1.f / l1;
    #pragma unroll
    for (int jd = 0; jd < 16; jd++) {
        const int d = jd * 8 + 2 * tg;
        const float o00 = oacc[jd][0] * i0, o01 = oacc[jd][1] * i0;
        const float o10 = oacc[jd][2] * i1, o11 = oacc[jd][3] * i1;
        const size_t idx0 = ((size_t)b * S_ + r0)     * H_ + head * HD + d;
        const size_t idx1 = ((size_t)b * S_ + r0 + 8) * H_ + head * HD + d;
        uint32_t h0 = packbf(o00, o01), h1 = packbf(o10, o11);
        __nv_bfloat162 hh0 = *(__nv_bfloat162*)&h0;
        __nv_bfloat162 hh1 = *(__nv_bfloat162*)&h1;
        uint32_t lo0 = packbf(o00 - __bfloat162float(hh0.x), o01 - __bfloat162float(hh0.y));
        uint32_t lo1 = packbf(o10 - __bfloat162float(hh1.x), o11 - __bfloat162float(hh1.y));
        *(uint32_t*)(Chi + idx0) = h0;  *(uint32_t*)(Clo + idx0) = lo0;
        *(uint32_t*)(Chi + idx1) = h1;  *(uint32_t*)(Clo + idx1) = lo1;
    }
}

// ---------------------------------------------------------------------------
extern "C" void kernel_launch(void* const* d_in, const int* in_sizes, int n_in,
                              void* d_out, int out_size)
{
    const float* x  = (const float*)d_in[0];
    const float* wq = (const float*)d_in[1];
    const float* bq = (const float*)d_in[2];
    const float* wk = (const float*)d_in[3];
    const float* bk = (const float*)d_in[4];
    const float* wv = (const float*)d_in[5];
    const float* bv = (const float*)d_in[6];
    const float* wo = (const float*)d_in[7];
    const float* bo = (const float*)d_in[8];
    float* out = (float*)d_out;

    __nv_bfloat16 *xhi, *xlo, *whi, *wlo;
    __nv_bfloat16 *qhi, *qlo, *khi, *klo, *vthi, *vtlo, *chi, *clo;
    cudaGetSymbolAddress((void**)&xhi, g_xhi);
    cudaGetSymbolAddress((void**)&xlo, g_xlo);
    cudaGetSymbolAddress((void**)&whi, g_whi);
    cudaGetSymbolAddress((void**)&wlo, g_wlo);
    cudaGetSymbolAddress((void**)&qhi, g_qhi);
    cudaGetSymbolAddress((void**)&qlo, g_qlo);
    cudaGetSymbolAddress((void**)&khi, g_khi);
    cudaGetSymbolAddress((void**)&klo, g_klo);
    cudaGetSymbolAddress((void**)&vthi, g_vthi);
    cudaGetSymbolAddress((void**)&vtlo, g_vtlo);
    cudaGetSymbolAddress((void**)&chi, g_chi);
    cudaGetSymbolAddress((void**)&clo, g_clo);

    static bool attr_set = false;
    if (!attr_set) {
        cudaFuncSetAttribute(gemm_bf16x3<0>, cudaFuncAttributeMaxDynamicSharedMemorySize, GEMM_SMEM_BYTES);
        cudaFuncSetAttribute(gemm_bf16x3<1>, cudaFuncAttributeMaxDynamicSharedMemorySize, GEMM_SMEM_BYTES);
        cudaFuncSetAttribute(gemm_bf16x3<2>, cudaFuncAttributeMaxDynamicSharedMemorySize, GEMM_SMEM_BYTES);
        cudaFuncSetAttribute(flash_attn_bf16, cudaFuncAttributeMaxDynamicSharedMemorySize, FL_SMEM_BYTES);
        attr_set = true;
    }

    const size_t WN = (size_t)H_ * H_;
    const float qscale = 0.08838834764831845f;   // 1/sqrt(128)

    split_bf16<<<1024, 256>>>(x,  xhi, xlo, M_*H_/4);
    split_bf16<<<512,  256>>>(wq, whi + 0*WN, wlo + 0*WN, H_*H_/4);
    split_bf16<<<512,  256>>>(wk, whi + 1*WN, wlo + 1*WN, H_*H_/4);
    split_bf16<<<512,  256>>>(wv, whi + 2*WN, wlo + 2*WN, H_*H_/4);
    split_bf16<<<512,  256>>>(wo, whi + 3*WN, wlo + 3*WN, H_*H_/4);

    dim3 gg(H_/128, M_/128);
    gemm_bf16x3<0><<<gg, 256, GEMM_SMEM_BYTES>>>(xhi, xlo, whi + 0*WN, wlo + 0*WN, bq, qscale, nullptr, qhi, qlo);
    gemm_bf16x3<0><<<gg, 256, GEMM_SMEM_BYTES>>>(xhi, xlo, whi + 1*WN, wlo + 1*WN, bk, 1.f,    nullptr, khi, klo);
    gemm_bf16x3<2><<<gg, 256, GEMM_SMEM_BYTES>>>(xhi, xlo, whi + 2*WN, wlo + 2*WN, bv, 1.f,    nullptr, vthi, vtlo);

    dim3 gf(NQ, B_*NH);   // (16, 32)
    flash_attn_bf16<<<gf, 256, FL_SMEM_BYTES>>>(qhi, qlo, khi, klo, vthi, vtlo, chi, clo);

    gemm_bf16x3<1><<<gg, 256, GEMM_SMEM_BYTES>>>(chi, clo, whi + 3*WN, wlo + 3*WN, bo, 1.f, out, nullptr, nullptr);
}